// round 5
// baseline (speedup 1.0000x reference)
#include <cuda_runtime.h>
#include <cuda_bf16.h>
#include <cstdint>
#include <cstddef>

// ---------------------------------------------------------------------------
// Problem constants
// ---------------------------------------------------------------------------
#define B_  256
#define T_  100
#define I_  1024
#define H_  2048
#define O_  10
#define M1  (B_ * T_)   // 25600

#define BK 32
#define STRIDE 40                    // padded bf16 row stride in smem
#define NSTAGE 4

// xin GEMM tiling (64x64)
#define BMX 64
#define BNX 64
#define SLOTX   (BMX * STRIDE)          // 2560 elems
#define ABYTESX (NSTAGE * SLOTX * 2)    // 20480 B per operand
#define SMEM_X  (4 * ABYTESX)           // 81920 B

// step tiling (32x64, 2 CTAs/SM)
#define BMS 32
#define BNS 64
#define SLOTA (BMS * STRIDE)            // 1280 elems
#define SLOTB (BNS * STRIDE)            // 2560 elems
#define SMEM_S ((2 * NSTAGE * SLOTA + 2 * NSTAGE * SLOTB) * 2)   // 61440 B
#define NBLK_STEP 256

// ---------------------------------------------------------------------------
// Device scratch
// ---------------------------------------------------------------------------
__device__ float g_xin [(size_t)T_ * B_ * H_];         // [t][b][h]
__device__ float g_hall[(size_t)T_ * B_ * H_];         // [t][b][h]
__device__ __nv_bfloat16 g_xhi[(size_t)M1 * I_];
__device__ __nv_bfloat16 g_xlo[(size_t)M1 * I_];
__device__ __nv_bfloat16 g_WinT_hi[(size_t)H_ * I_];   // [h][i]
__device__ __nv_bfloat16 g_WinT_lo[(size_t)H_ * I_];
__device__ __nv_bfloat16 g_WT_hi[(size_t)H_ * H_];     // [n][k]
__device__ __nv_bfloat16 g_WT_lo[(size_t)H_ * H_];
__device__ __nv_bfloat16 g_hA_hi[(size_t)B_ * H_], g_hA_lo[(size_t)B_ * H_];
__device__ __nv_bfloat16 g_hB_hi[(size_t)B_ * H_], g_hB_lo[(size_t)B_ * H_];
__device__ unsigned g_bar_count = 0;
__device__ unsigned g_bar_sense = 0;

// ---------------------------------------------------------------------------
// Helpers
// ---------------------------------------------------------------------------
__device__ __forceinline__ uint32_t s2u(const void* p) {
    uint32_t a;
    asm("{ .reg .u64 t; cvta.to.shared.u64 t, %1; cvt.u32.u64 %0, t; }" : "=r"(a) : "l"(p));
    return a;
}
__device__ __forceinline__ void cp16(uint32_t s, const void* g) {
    asm volatile("cp.async.cg.shared.global [%0], [%1], 16;" :: "r"(s), "l"(g));
}
#define CP_COMMIT()  asm volatile("cp.async.commit_group;")
#define CP_WAIT(N)   asm volatile("cp.async.wait_group %0;" :: "n"(N))

__device__ __forceinline__ void mma_bf16(float* d, const uint32_t* a, uint32_t b0, uint32_t b1) {
    asm volatile(
        "mma.sync.aligned.m16n8k16.row.col.f32.bf16.bf16.f32 "
        "{%0,%1,%2,%3}, {%4,%5,%6,%7}, {%8,%9}, {%0,%1,%2,%3};"
        : "+f"(d[0]), "+f"(d[1]), "+f"(d[2]), "+f"(d[3])
        : "r"(a[0]), "r"(a[1]), "r"(a[2]), "r"(a[3]), "r"(b0), "r"(b1));
}
__device__ __forceinline__ void split2(float v, __nv_bfloat16& h, __nv_bfloat16& l) {
    h = __float2bfloat16(v);
    l = __float2bfloat16(v - __bfloat162float(h));
}

// bf16x3 compute on one smem stage.
// Warp tile: m16 x (8*NJ).  mrow = warp m offset (rows), ncol = warp n offset.
template<int NJ>
__device__ __forceinline__ void compute_stage(
    const __nv_bfloat16* sAh, const __nv_bfloat16* sAl,
    const __nv_bfloat16* sBh, const __nv_bfloat16* sBl,
    int mrow, int ncol, int g, int tg, float (*d)[4])
{
    const int ar0 = (mrow + g) * STRIDE;
    const int ar1 = ar0 + 8 * STRIDE;
    #pragma unroll
    for (int kh = 0; kh < 2; kh++) {
        const int kb = kh * 16 + 2 * tg;
        uint32_t ah[4], al[4];
        ah[0] = *(const uint32_t*)&sAh[ar0 + kb];
        ah[1] = *(const uint32_t*)&sAh[ar1 + kb];
        ah[2] = *(const uint32_t*)&sAh[ar0 + kb + 8];
        ah[3] = *(const uint32_t*)&sAh[ar1 + kb + 8];
        al[0] = *(const uint32_t*)&sAl[ar0 + kb];
        al[1] = *(const uint32_t*)&sAl[ar1 + kb];
        al[2] = *(const uint32_t*)&sAl[ar0 + kb + 8];
        al[3] = *(const uint32_t*)&sAl[ar1 + kb + 8];
        #pragma unroll
        for (int j = 0; j < NJ; j++) {
            const int nb = (ncol + j * 8 + g) * STRIDE + kb;
            uint32_t bh0 = *(const uint32_t*)&sBh[nb];
            uint32_t bh1 = *(const uint32_t*)&sBh[nb + 8];
            uint32_t bl0 = *(const uint32_t*)&sBl[nb];
            uint32_t bl1 = *(const uint32_t*)&sBl[nb + 8];
            mma_bf16(d[j], ah, bh0, bh1);
            mma_bf16(d[j], ah, bl0, bl1);
            mma_bf16(d[j], al, bh0, bh1);
        }
    }
}

// ---------------------------------------------------------------------------
// Prologue kernels
// ---------------------------------------------------------------------------
__global__ void decomp_kernel(const float* __restrict__ src,
                              __nv_bfloat16* __restrict__ hi,
                              __nv_bfloat16* __restrict__ lo, size_t n4) {
    for (size_t i = (size_t)blockIdx.x * blockDim.x + threadIdx.x; i < n4;
         i += (size_t)gridDim.x * blockDim.x) {
        float4 v = ((const float4*)src)[i];
        __nv_bfloat16 h0, l0, h1, l1, h2, l2, h3, l3;
        split2(v.x, h0, l0); split2(v.y, h1, l1);
        split2(v.z, h2, l2); split2(v.w, h3, l3);
        ((__nv_bfloat162*)hi)[i * 2 + 0] = __halves2bfloat162(h0, h1);
        ((__nv_bfloat162*)hi)[i * 2 + 1] = __halves2bfloat162(h2, h3);
        ((__nv_bfloat162*)lo)[i * 2 + 0] = __halves2bfloat162(l0, l1);
        ((__nv_bfloat162*)lo)[i * 2 + 1] = __halves2bfloat162(l2, l3);
    }
}

__global__ void transpose_decomp_kernel(const float* __restrict__ src, int R, int C,
                                        __nv_bfloat16* __restrict__ dhi,
                                        __nv_bfloat16* __restrict__ dlo) {
    __shared__ float tile[32][33];
    const int bx = blockIdx.x * 32;
    const int by = blockIdx.y * 32;
    const int tx = threadIdx.x, ty = threadIdx.y;
    #pragma unroll
    for (int j = 0; j < 32; j += 8)
        tile[ty + j][tx] = src[(size_t)(by + ty + j) * C + bx + tx];
    __syncthreads();
    #pragma unroll
    for (int j = 0; j < 32; j += 8) {
        float v = tile[tx][ty + j];
        size_t o = (size_t)(bx + ty + j) * R + by + tx;
        __nv_bfloat16 h, l; split2(v, h, l);
        dhi[o] = h; dlo[o] = l;
    }
}

// ---------------------------------------------------------------------------
// xin GEMM: g_xin[t][b][:] = x @ Win.  64x64 tiles, warp m16n32.
// ---------------------------------------------------------------------------
__global__ void __launch_bounds__(256) xin_gemm_kernel() {
    extern __shared__ __nv_bfloat16 sm[];
    __nv_bfloat16* pAh = sm;
    __nv_bfloat16* pAl = sm + 1 * NSTAGE * SLOTX;
    __nv_bfloat16* pBh = sm + 2 * NSTAGE * SLOTX;
    __nv_bfloat16* pBl = sm + 3 * NSTAGE * SLOTX;
    const uint32_t sbase = s2u(sm);

    const int tid = threadIdx.x;
    const int wid = tid >> 5, lane = tid & 31;
    const int g = lane >> 2, tg = lane & 3;
    const int mrow = (wid & 3) * 16;
    const int ncol = (wid >> 2) * 32;
    const int rowBase = blockIdx.y * BMX;
    const int colBase = blockIdx.x * BNX;
    const int lr = tid >> 2, lc = (tid & 3) * 8;
    constexpr int NK = I_ / BK;   // 32

    auto issue = [&](int slot, int kc) {
        const int k0 = kc * BK;
        const size_t ga = (size_t)(rowBase + lr) * I_ + k0 + lc;
        const size_t gb = (size_t)(colBase + lr) * I_ + k0 + lc;
        const uint32_t so = (uint32_t)(slot * SLOTX + lr * STRIDE + lc) * 2;
        cp16(sbase + 0 * ABYTESX + so, g_xhi + ga);
        cp16(sbase + 1 * ABYTESX + so, g_xlo + ga);
        cp16(sbase + 2 * ABYTESX + so, g_WinT_hi + gb);
        cp16(sbase + 3 * ABYTESX + so, g_WinT_lo + gb);
        CP_COMMIT();
    };

    issue(0, 0); issue(1, 1); issue(2, 2);
    float d[4][4] = {};

    #pragma unroll 1
    for (int kc = 0; kc < NK; kc++) {
        CP_WAIT(2);
        __syncthreads();
        if (kc + 3 < NK) issue((kc + 3) & 3, kc + 3);
        const int s = (kc & 3) * SLOTX;
        compute_stage<4>(pAh + s, pAl + s, pBh + s, pBl + s, mrow, ncol, g, tg, d);
    }
    CP_WAIT(0);

    const int r0 = rowBase + mrow + g;
    const int r1 = r0 + 8;
    const int bb0 = r0 / T_, tt0 = r0 - bb0 * T_;
    const int bb1 = r1 / T_, tt1 = r1 - bb1 * T_;
    #pragma unroll
    for (int j = 0; j < 4; j++) {
        const int col = colBase + ncol + j * 8 + 2 * tg;
        *(float2*)&g_xin[((size_t)tt0 * B_ + bb0) * H_ + col] = make_float2(d[j][0], d[j][1]);
        *(float2*)&g_xin[((size_t)tt1 * B_ + bb1) * H_ + col] = make_float2(d[j][2], d[j][3]);
    }
}

// ---------------------------------------------------------------------------
// Persistent recurrence kernel: 32x64 tiles, grid 256 = 2 CTAs/SM.
// ---------------------------------------------------------------------------
__device__ __forceinline__ void grid_barrier(unsigned target) {
    __threadfence();
    __syncthreads();
    if (threadIdx.x == 0) {
        unsigned a = atomicAdd(&g_bar_count, 1);
        if (a == NBLK_STEP - 1) {
            atomicExch(&g_bar_count, 0);
            atomicExch(&g_bar_sense, target);
        } else {
            while (atomicAdd(&g_bar_sense, 0) < target) { __nanosleep(64); }
        }
    }
    __syncthreads();
}

__global__ void __launch_bounds__(256, 2) step_persistent_kernel() {
    extern __shared__ __nv_bfloat16 sm[];
    __nv_bfloat16* pAh = sm;                                   // NSTAGE*SLOTA
    __nv_bfloat16* pAl = sm + NSTAGE * SLOTA;
    __nv_bfloat16* pBh = sm + 2 * NSTAGE * SLOTA;              // NSTAGE*SLOTB
    __nv_bfloat16* pBl = sm + 2 * NSTAGE * SLOTA + NSTAGE * SLOTB;
    const uint32_t sbase  = s2u(sm);
    const uint32_t oAl = NSTAGE * SLOTA * 2;
    const uint32_t oBh = 2 * NSTAGE * SLOTA * 2;
    const uint32_t oBl = oBh + NSTAGE * SLOTB * 2;

    const int tid = threadIdx.x;
    const int wid = tid >> 5, lane = tid & 31;
    const int g = lane >> 2, tg = lane & 3;
    const int mrow = (wid & 1) * 16;        // 2 m-tiles
    const int ncol = (wid >> 1) * 16;       // 4 n-tiles of 16
    const int bid = blockIdx.x;
    const int rowBase = (bid >> 5) * BMS;   // 8 row tiles (B=256)
    const int colBase = (bid & 31) * BNS;   // 32 col tiles (H=2048)
    const int lr = tid >> 2, lc = (tid & 3) * 8;   // A loader: threads 0..127
    constexpr int NK = H_ / BK;   // 64

    __shared__ unsigned s_base;
    if (tid == 0) s_base = atomicAdd(&g_bar_sense, 0u);
    __syncthreads();
    const unsigned base = s_base;

    #pragma unroll 1
    for (int t = 0; t < T_; t++) {
        const __nv_bfloat16* ah  = (t & 1) ? g_hB_hi : g_hA_hi;
        const __nv_bfloat16* al  = (t & 1) ? g_hB_lo : g_hA_lo;
        __nv_bfloat16* whi = (t & 1) ? g_hA_hi : g_hB_hi;
        __nv_bfloat16* wlo = (t & 1) ? g_hA_lo : g_hB_lo;

        auto issue = [&](int slot, int kc) {
            const int k0 = kc * BK;
            if (tid < 128) {   // A: 32 rows x 32 k, 4 threads/row
                const size_t ga = (size_t)(rowBase + lr) * H_ + k0 + lc;
                const uint32_t so = (uint32_t)(slot * SLOTA + lr * STRIDE + lc) * 2;
                cp16(sbase + so, ah + ga);
                cp16(sbase + oAl + so, al + ga);
            }
            {                  // B: 64 rows x 32 k, all 256 threads
                const size_t gb = (size_t)(colBase + lr) * H_ + k0 + lc;
                const uint32_t so = (uint32_t)(slot * SLOTB + lr * STRIDE + lc) * 2;
                cp16(sbase + oBh + so, g_WT_hi + gb);
                cp16(sbase + oBl + so, g_WT_lo + gb);
            }
            CP_COMMIT();
        };

        issue(0, 0); issue(1, 1); issue(2, 2);
        float d[2][4] = {};

        #pragma unroll 1
        for (int kc = 0; kc < NK; kc++) {
            CP_WAIT(2);
            __syncthreads();
            if (kc + 3 < NK) issue((kc + 3) & 3, kc + 3);
            compute_stage<2>(pAh + (kc & 3) * SLOTA, pAl + (kc & 3) * SLOTA,
                             pBh + (kc & 3) * SLOTB, pBl + (kc & 3) * SLOTB,
                             mrow, ncol, g, tg, d);
        }
        CP_WAIT(0);

        // epilogue: h = tanh(xin + acc); fp32 + hi/lo split stores
        const int r0 = rowBase + mrow + g;
        const int r1 = r0 + 8;
        #pragma unroll
        for (int j = 0; j < 2; j++) {
            const int col = colBase + ncol + j * 8 + 2 * tg;
            const size_t o0 = ((size_t)t * B_ + r0) * H_ + col;
            const size_t o1 = ((size_t)t * B_ + r1) * H_ + col;
            float2 x0 = *(const float2*)&g_xin[o0];
            float2 x1 = *(const float2*)&g_xin[o1];
            float h00 = tanhf(x0.x + d[j][0]);
            float h01 = tanhf(x0.y + d[j][1]);
            float h10 = tanhf(x1.x + d[j][2]);
            float h11 = tanhf(x1.y + d[j][3]);
            *(float2*)&g_hall[o0] = make_float2(h00, h01);
            *(float2*)&g_hall[o1] = make_float2(h10, h11);
            __nv_bfloat16 e0, f0, e1, f1, e2, f2, e3, f3;
            split2(h00, e0, f0); split2(h01, e1, f1);
            split2(h10, e2, f2); split2(h11, e3, f3);
            const size_t w0 = (size_t)r0 * H_ + col;
            const size_t w1 = (size_t)r1 * H_ + col;
            *(__nv_bfloat162*)&whi[w0] = __halves2bfloat162(e0, e1);
            *(__nv_bfloat162*)&wlo[w0] = __halves2bfloat162(f0, f1);
            *(__nv_bfloat162*)&whi[w1] = __halves2bfloat162(e2, e3);
            *(__nv_bfloat162*)&wlo[w1] = __halves2bfloat162(f2, f3);
        }

        if (t < T_ - 1) grid_barrier(base + (unsigned)t + 1u);
    }
}

// ---------------------------------------------------------------------------
// Output head
// ---------------------------------------------------------------------------
__global__ void __launch_bounds__(256) out_kernel(
    const float* __restrict__ lin_w,
    const float* __restrict__ lin_b,
    float* __restrict__ out)
{
    const int bt = blockIdx.x;
    const int t = bt / B_;
    const int b = bt % B_;
    const int tid = threadIdx.x;

    const float* hrow = g_hall + ((size_t)t * B_ + b) * H_;

    float hreg[H_ / 256];
    #pragma unroll
    for (int i = 0; i < H_ / 256; i++)
        hreg[i] = hrow[i * 256 + tid];

    float acc[O_];
    #pragma unroll
    for (int o = 0; o < O_; o++) {
        float s = 0.f;
        #pragma unroll
        for (int i = 0; i < H_ / 256; i++)
            s += hreg[i] * lin_w[(size_t)o * H_ + i * 256 + tid];
        acc[o] = s;
    }

    #pragma unroll
    for (int off = 16; off > 0; off >>= 1)
        #pragma unroll
        for (int o = 0; o < O_; o++)
            acc[o] += __shfl_xor_sync(0xFFFFFFFFu, acc[o], off);

    __shared__ float wsum[8][O_];
    const int lane = tid & 31;
    const int w = tid >> 5;
    if (lane == 0)
        #pragma unroll
        for (int o = 0; o < O_; o++)
            wsum[w][o] = acc[o];
    __syncthreads();

    if (tid < O_) {
        float s = lin_b[tid];
        #pragma unroll
        for (int ww = 0; ww < 8; ww++)
            s += wsum[ww][tid];
        out[((size_t)b * T_ + t) * O_ + tid] = s;
    }
}

// ---------------------------------------------------------------------------
extern "C" void kernel_launch(void* const* d_in, const int* in_sizes, int n_in,
                              void* d_out, int out_size)
{
    const float* x     = (const float*)d_in[0];
    const float* h0    = (const float*)d_in[1];
    const float* Win   = (const float*)d_in[2];
    const float* W     = (const float*)d_in[3];
    const float* lin_w = (const float*)d_in[4];
    const float* lin_b = (const float*)d_in[5];
    float* out = (float*)d_out;

    __nv_bfloat16 *xhi, *xlo, *winT_hi, *winT_lo, *wT_hi, *wT_lo, *hA_hi, *hA_lo;
    cudaGetSymbolAddress((void**)&xhi, g_xhi);
    cudaGetSymbolAddress((void**)&xlo, g_xlo);
    cudaGetSymbolAddress((void**)&winT_hi, g_WinT_hi);
    cudaGetSymbolAddress((void**)&winT_lo, g_WinT_lo);
    cudaGetSymbolAddress((void**)&wT_hi, g_WT_hi);
    cudaGetSymbolAddress((void**)&wT_lo, g_WT_lo);
    cudaGetSymbolAddress((void**)&hA_hi, g_hA_hi);
    cudaGetSymbolAddress((void**)&hA_lo, g_hA_lo);

    static bool attr_done = false;
    if (!attr_done) {
        cudaFuncSetAttribute(xin_gemm_kernel,
                             cudaFuncAttributeMaxDynamicSharedMemorySize, SMEM_X);
        cudaFuncSetAttribute(step_persistent_kernel,
                             cudaFuncAttributeMaxDynamicSharedMemorySize, SMEM_S);
        attr_done = true;
    }

    // Prologue
    decomp_kernel<<<4096, 256>>>(x, xhi, xlo, (size_t)M1 * I_ / 4);
    decomp_kernel<<<512, 256>>>(h0, hA_hi, hA_lo, (size_t)B_ * H_ / 4);
    transpose_decomp_kernel<<<dim3(H_ / 32, I_ / 32), dim3(32, 8)>>>(Win, I_, H_, winT_hi, winT_lo);
    transpose_decomp_kernel<<<dim3(H_ / 32, H_ / 32), dim3(32, 8)>>>(W, H_, H_, wT_hi, wT_lo);

    // Input projection
    xin_gemm_kernel<<<dim3(H_ / BNX, M1 / BMX), 256, SMEM_X>>>();

    // Full recurrence
    step_persistent_kernel<<<NBLK_STEP, 256, SMEM_S>>>();

    // Output head
    out_kernel<<<T_ * B_, 256>>>(lin_w, lin_b, out);
}

// round 6
// speedup vs baseline: 1.1890x; 1.1890x over previous
#include <cuda_runtime.h>
#include <cuda_bf16.h>
#include <cstdint>
#include <cstddef>

// ---------------------------------------------------------------------------
// Problem constants
// ---------------------------------------------------------------------------
#define B_  256
#define T_  100
#define I_  1024
#define H_  2048
#define O_  10
#define M1  (B_ * T_)   // 25600

// GEMM tiling (both kernels: 64x64 CTA tile, warp 16x32, 8 warps)
#define BM 64
#define BN 64
#define BK 32
#define STRIDE 40                    // padded bf16 row stride in smem (80B rows)
#define NSTAGE 4
#define SLOT   (BM * STRIDE)         // 2560 elems per array per stage
#define ABYTES (NSTAGE * SLOT * 2)   // 20480 bytes per operand array
#define SMEM_BYTES (4 * ABYTES)      // 81920 bytes

#define NBLK_STEP 128                // persistent grid size (1 CTA/SM wave)

// ---------------------------------------------------------------------------
// Device scratch
// ---------------------------------------------------------------------------
__device__ float g_xin [(size_t)T_ * B_ * H_];         // [t][b][h]
__device__ float g_hall[(size_t)T_ * B_ * H_];         // [t][b][h]
__device__ __nv_bfloat16 g_xhi[(size_t)M1 * I_];
__device__ __nv_bfloat16 g_xlo[(size_t)M1 * I_];
__device__ __nv_bfloat16 g_WinT_hi[(size_t)H_ * I_];   // [h][i]
__device__ __nv_bfloat16 g_WinT_lo[(size_t)H_ * I_];
__device__ __nv_bfloat16 g_WT_hi[(size_t)H_ * H_];     // [n][k]
__device__ __nv_bfloat16 g_WT_lo[(size_t)H_ * H_];
__device__ __nv_bfloat16 g_hA_hi[(size_t)B_ * H_], g_hA_lo[(size_t)B_ * H_];
__device__ __nv_bfloat16 g_hB_hi[(size_t)B_ * H_], g_hB_lo[(size_t)B_ * H_];
__device__ unsigned g_bar_count = 0;
__device__ unsigned g_bar_sense = 0;

// ---------------------------------------------------------------------------
// Helpers
// ---------------------------------------------------------------------------
__device__ __forceinline__ uint32_t s2u(const void* p) {
    uint32_t a;
    asm("{ .reg .u64 t; cvta.to.shared.u64 t, %1; cvt.u32.u64 %0, t; }" : "=r"(a) : "l"(p));
    return a;
}
__device__ __forceinline__ void cp16(uint32_t s, const void* g) {
    asm volatile("cp.async.cg.shared.global [%0], [%1], 16;" :: "r"(s), "l"(g));
}
#define CP_COMMIT()  asm volatile("cp.async.commit_group;")
#define CP_WAIT(N)   asm volatile("cp.async.wait_group %0;" :: "n"(N))

__device__ __forceinline__ void mma_bf16(float* d, const uint32_t* a, uint32_t b0, uint32_t b1) {
    asm volatile(
        "mma.sync.aligned.m16n8k16.row.col.f32.bf16.bf16.f32 "
        "{%0,%1,%2,%3}, {%4,%5,%6,%7}, {%8,%9}, {%0,%1,%2,%3};"
        : "+f"(d[0]), "+f"(d[1]), "+f"(d[2]), "+f"(d[3])
        : "r"(a[0]), "r"(a[1]), "r"(a[2]), "r"(a[3]), "r"(b0), "r"(b1));
}
// ldmatrix x4: loads 4 8x8 b16 tiles; per-thread address = row start.
__device__ __forceinline__ void ldsm4(uint32_t* r, uint32_t addr) {
    asm volatile("ldmatrix.sync.aligned.m8n8.x4.shared.b16 {%0,%1,%2,%3}, [%4];"
        : "=r"(r[0]), "=r"(r[1]), "=r"(r[2]), "=r"(r[3]) : "r"(addr));
}
__device__ __forceinline__ void split2(float v, __nv_bfloat16& h, __nv_bfloat16& l) {
    h = __float2bfloat16(v);
    l = __float2bfloat16(v - __bfloat162float(h));
}

// bf16x3 compute on one smem stage via ldmatrix.
// A lane-address mapping (x4 -> a0..a3 of m16n8k16):
//   lanes 0-7:rows 0-7,k+0 | 8-15:rows 8-15,k+0 | 16-23:rows 0-7,k+8 | 24-31:rows 8-15,k+8
// B (stored [n][k]) lane mapping (x4 -> {b0,b1} of n-tile jp*2 and jp*2+1):
//   lanes 0-7:n 0-7,k+0 | 8-15:n 0-7,k+8 | 16-23:n 8-15,k+0 | 24-31:n 8-15,k+8
__device__ __forceinline__ void compute_stage_lm(
    uint32_t sAh, uint32_t sAl, uint32_t sBh, uint32_t sBl,
    uint32_t a_off, uint32_t b_off0, uint32_t b_off1, float (*d)[4])
{
    #pragma unroll
    for (int kh = 0; kh < 2; kh++) {
        const uint32_t ko = kh * 32;   // 16 elems = 32 bytes
        uint32_t ah[4], al[4], bh[4], bl[4];
        ldsm4(ah, sAh + a_off + ko);
        ldsm4(al, sAl + a_off + ko);
        ldsm4(bh, sBh + b_off0 + ko);
        ldsm4(bl, sBl + b_off0 + ko);
        mma_bf16(d[0], ah, bh[0], bh[1]);
        mma_bf16(d[0], ah, bl[0], bl[1]);
        mma_bf16(d[0], al, bh[0], bh[1]);
        mma_bf16(d[1], ah, bh[2], bh[3]);
        mma_bf16(d[1], ah, bl[2], bl[3]);
        mma_bf16(d[1], al, bh[2], bh[3]);
        ldsm4(bh, sBh + b_off1 + ko);
        ldsm4(bl, sBl + b_off1 + ko);
        mma_bf16(d[2], ah, bh[0], bh[1]);
        mma_bf16(d[2], ah, bl[0], bl[1]);
        mma_bf16(d[2], al, bh[0], bh[1]);
        mma_bf16(d[3], ah, bh[2], bh[3]);
        mma_bf16(d[3], ah, bl[2], bl[3]);
        mma_bf16(d[3], al, bh[2], bh[3]);
    }
}

// Lane offsets (bytes) for ldmatrix addressing
__device__ __forceinline__ uint32_t a_lane_off(int mrow, int lane) {
    return (uint32_t)(((mrow + (lane & 15)) * STRIDE + ((lane >> 4) & 1) * 8) * 2);
}
__device__ __forceinline__ uint32_t b_lane_off(int ncol, int jp, int lane) {
    return (uint32_t)(((ncol + jp * 16 + ((lane >> 4) & 1) * 8 + (lane & 7)) * STRIDE
                       + ((lane >> 3) & 1) * 8) * 2);
}

// ---------------------------------------------------------------------------
// Prologue kernels
// ---------------------------------------------------------------------------
__global__ void decomp_kernel(const float* __restrict__ src,
                              __nv_bfloat16* __restrict__ hi,
                              __nv_bfloat16* __restrict__ lo, size_t n4) {
    for (size_t i = (size_t)blockIdx.x * blockDim.x + threadIdx.x; i < n4;
         i += (size_t)gridDim.x * blockDim.x) {
        float4 v = ((const float4*)src)[i];
        __nv_bfloat16 h0, l0, h1, l1, h2, l2, h3, l3;
        split2(v.x, h0, l0); split2(v.y, h1, l1);
        split2(v.z, h2, l2); split2(v.w, h3, l3);
        ((__nv_bfloat162*)hi)[i * 2 + 0] = __halves2bfloat162(h0, h1);
        ((__nv_bfloat162*)hi)[i * 2 + 1] = __halves2bfloat162(h2, h3);
        ((__nv_bfloat162*)lo)[i * 2 + 0] = __halves2bfloat162(l0, l1);
        ((__nv_bfloat162*)lo)[i * 2 + 1] = __halves2bfloat162(l2, l3);
    }
}

__global__ void transpose_decomp_kernel(const float* __restrict__ src, int R, int C,
                                        __nv_bfloat16* __restrict__ dhi,
                                        __nv_bfloat16* __restrict__ dlo) {
    __shared__ float tile[32][33];
    const int bx = blockIdx.x * 32;
    const int by = blockIdx.y * 32;
    const int tx = threadIdx.x, ty = threadIdx.y;
    #pragma unroll
    for (int j = 0; j < 32; j += 8)
        tile[ty + j][tx] = src[(size_t)(by + ty + j) * C + bx + tx];
    __syncthreads();
    #pragma unroll
    for (int j = 0; j < 32; j += 8) {
        float v = tile[tx][ty + j];
        size_t o = (size_t)(bx + ty + j) * R + by + tx;
        __nv_bfloat16 h, l; split2(v, h, l);
        dhi[o] = h; dlo[o] = l;
    }
}

// ---------------------------------------------------------------------------
// xin GEMM: g_xin[t][b][:] = x @ Win
// ---------------------------------------------------------------------------
__global__ void __launch_bounds__(256) xin_gemm_kernel() {
    extern __shared__ __nv_bfloat16 sm[];
    const uint32_t sbase = s2u(sm);
    const uint32_t pAh = sbase;
    const uint32_t pAl = sbase + 1 * ABYTES;
    const uint32_t pBh = sbase + 2 * ABYTES;
    const uint32_t pBl = sbase + 3 * ABYTES;

    const int tid = threadIdx.x;
    const int wid = tid >> 5, lane = tid & 31;
    const int mrow = (wid & 3) * 16;
    const int ncol = (wid >> 2) * 32;
    const int rowBase = blockIdx.y * BM;
    const int colBase = blockIdx.x * BN;
    const int lr = tid >> 2, lc = (tid & 3) * 8;
    constexpr int NK = I_ / BK;   // 32

    const uint32_t a_off  = a_lane_off(mrow, lane);
    const uint32_t b_off0 = b_lane_off(ncol, 0, lane);
    const uint32_t b_off1 = b_lane_off(ncol, 1, lane);

    auto issue = [&](int slot, int kc) {
        const int k0 = kc * BK;
        const size_t ga = (size_t)(rowBase + lr) * I_ + k0 + lc;
        const size_t gb = (size_t)(colBase + lr) * I_ + k0 + lc;
        const uint32_t so = (uint32_t)(slot * SLOT + lr * STRIDE + lc) * 2;
        cp16(pAh + so, g_xhi + ga);
        cp16(pAl + so, g_xlo + ga);
        cp16(pBh + so, g_WinT_hi + gb);
        cp16(pBl + so, g_WinT_lo + gb);
        CP_COMMIT();
    };

    issue(0, 0); issue(1, 1); issue(2, 2);
    float d[4][4] = {};

    #pragma unroll 1
    for (int kc = 0; kc < NK; kc++) {
        CP_WAIT(2);
        __syncthreads();
        if (kc + 3 < NK) issue((kc + 3) & 3, kc + 3);
        const uint32_t so = (uint32_t)((kc & 3) * SLOT) * 2;
        compute_stage_lm(pAh + so, pAl + so, pBh + so, pBl + so,
                         a_off, b_off0, b_off1, d);
    }
    CP_WAIT(0);

    const int g = lane >> 2, tg = lane & 3;
    const int r0 = rowBase + mrow + g;
    const int r1 = r0 + 8;
    const int bb0 = r0 / T_, tt0 = r0 - bb0 * T_;
    const int bb1 = r1 / T_, tt1 = r1 - bb1 * T_;
    #pragma unroll
    for (int j = 0; j < 4; j++) {
        const int col = colBase + ncol + j * 8 + 2 * tg;
        *(float2*)&g_xin[((size_t)tt0 * B_ + bb0) * H_ + col] = make_float2(d[j][0], d[j][1]);
        *(float2*)&g_xin[((size_t)tt1 * B_ + bb1) * H_ + col] = make_float2(d[j][2], d[j][3]);
    }
}

// ---------------------------------------------------------------------------
// Persistent recurrence kernel: 64x64 tiles, grid 128 (1 CTA/SM).
// ---------------------------------------------------------------------------
__device__ __forceinline__ void grid_barrier(unsigned target) {
    __threadfence();
    __syncthreads();
    if (threadIdx.x == 0) {
        unsigned a = atomicAdd(&g_bar_count, 1);
        if (a == NBLK_STEP - 1) {
            atomicExch(&g_bar_count, 0);
            atomicExch(&g_bar_sense, target);
        } else {
            while (atomicAdd(&g_bar_sense, 0) < target) { __nanosleep(64); }
        }
    }
    __syncthreads();
}

__global__ void __launch_bounds__(256) step_persistent_kernel() {
    extern __shared__ __nv_bfloat16 sm[];
    const uint32_t sbase = s2u(sm);
    const uint32_t pAh = sbase;
    const uint32_t pAl = sbase + 1 * ABYTES;
    const uint32_t pBh = sbase + 2 * ABYTES;
    const uint32_t pBl = sbase + 3 * ABYTES;

    const int tid = threadIdx.x;
    const int wid = tid >> 5, lane = tid & 31;
    const int mrow = (wid & 3) * 16;
    const int ncol = (wid >> 2) * 32;
    const int bid = blockIdx.x;
    const int rowBase = (bid >> 5) * BM;   // 4 row tiles (B=256)
    const int colBase = (bid & 31) * BN;   // 32 col tiles (H=2048)
    const int lr = tid >> 2, lc = (tid & 3) * 8;
    constexpr int NK = H_ / BK;   // 64

    const uint32_t a_off  = a_lane_off(mrow, lane);
    const uint32_t b_off0 = b_lane_off(ncol, 0, lane);
    const uint32_t b_off1 = b_lane_off(ncol, 1, lane);

    __shared__ unsigned s_base;
    if (tid == 0) s_base = atomicAdd(&g_bar_sense, 0u);
    __syncthreads();
    const unsigned base = s_base;

    #pragma unroll 1
    for (int t = 0; t < T_; t++) {
        const __nv_bfloat16* ah  = (t & 1) ? g_hB_hi : g_hA_hi;
        const __nv_bfloat16* al  = (t & 1) ? g_hB_lo : g_hA_lo;
        __nv_bfloat16* whi = (t & 1) ? g_hA_hi : g_hB_hi;
        __nv_bfloat16* wlo = (t & 1) ? g_hA_lo : g_hB_lo;

        auto issue = [&](int slot, int kc) {
            const int k0 = kc * BK;
            const size_t ga = (size_t)(rowBase + lr) * H_ + k0 + lc;
            const size_t gb = (size_t)(colBase + lr) * H_ + k0 + lc;
            const uint32_t so = (uint32_t)(slot * SLOT + lr * STRIDE + lc) * 2;
            cp16(pAh + so, ah + ga);
            cp16(pAl + so, al + ga);
            cp16(pBh + so, g_WT_hi + gb);
            cp16(pBl + so, g_WT_lo + gb);
            CP_COMMIT();
        };

        issue(0, 0); issue(1, 1); issue(2, 2);
        float d[4][4] = {};

        #pragma unroll 1
        for (int kc = 0; kc < NK; kc++) {
            CP_WAIT(2);
            __syncthreads();
            if (kc + 3 < NK) issue((kc + 3) & 3, kc + 3);
            const uint32_t so = (uint32_t)((kc & 3) * SLOT) * 2;
            compute_stage_lm(pAh + so, pAl + so, pBh + so, pBl + so,
                             a_off, b_off0, b_off1, d);
        }
        CP_WAIT(0);   // drain own groups before next t reuses slots

        // epilogue: h = tanh(xin + acc); fp32 + hi/lo split stores
        const int g = lane >> 2, tg = lane & 3;
        const int r0 = rowBase + mrow + g;
        const int r1 = r0 + 8;
        #pragma unroll
        for (int j = 0; j < 4; j++) {
            const int col = colBase + ncol + j * 8 + 2 * tg;
            const size_t o0 = ((size_t)t * B_ + r0) * H_ + col;
            const size_t o1 = ((size_t)t * B_ + r1) * H_ + col;
            float2 x0 = *(const float2*)&g_xin[o0];
            float2 x1 = *(const float2*)&g_xin[o1];
            float h00 = tanhf(x0.x + d[j][0]);
            float h01 = tanhf(x0.y + d[j][1]);
            float h10 = tanhf(x1.x + d[j][2]);
            float h11 = tanhf(x1.y + d[j][3]);
            *(float2*)&g_hall[o0] = make_float2(h00, h01);
            *(float2*)&g_hall[o1] = make_float2(h10, h11);
            __nv_bfloat16 e0, f0, e1, f1, e2, f2, e3, f3;
            split2(h00, e0, f0); split2(h01, e1, f1);
            split2(h10, e2, f2); split2(h11, e3, f3);
            const size_t w0 = (size_t)r0 * H_ + col;
            const size_t w1 = (size_t)r1 * H_ + col;
            *(__nv_bfloat162*)&whi[w0] = __halves2bfloat162(e0, e1);
            *(__nv_bfloat162*)&wlo[w0] = __halves2bfloat162(f0, f1);
            *(__nv_bfloat162*)&whi[w1] = __halves2bfloat162(e2, e3);
            *(__nv_bfloat162*)&wlo[w1] = __halves2bfloat162(f2, f3);
        }

        if (t < T_ - 1) grid_barrier(base + (unsigned)t + 1u);
    }
}

// ---------------------------------------------------------------------------
// Output head
// ---------------------------------------------------------------------------
__global__ void __launch_bounds__(256) out_kernel(
    const float* __restrict__ lin_w,
    const float* __restrict__ lin_b,
    float* __restrict__ out)
{
    const int bt = blockIdx.x;
    const int t = bt / B_;
    const int b = bt % B_;
    const int tid = threadIdx.x;

    const float* hrow = g_hall + ((size_t)t * B_ + b) * H_;

    float hreg[H_ / 256];
    #pragma unroll
    for (int i = 0; i < H_ / 256; i++)
        hreg[i] = hrow[i * 256 + tid];

    float acc[O_];
    #pragma unroll
    for (int o = 0; o < O_; o++) {
        float s = 0.f;
        #pragma unroll
        for (int i = 0; i < H_ / 256; i++)
            s += hreg[i] * lin_w[(size_t)o * H_ + i * 256 + tid];
        acc[o] = s;
    }

    #pragma unroll
    for (int off = 16; off > 0; off >>= 1)
        #pragma unroll
        for (int o = 0; o < O_; o++)
            acc[o] += __shfl_xor_sync(0xFFFFFFFFu, acc[o], off);

    __shared__ float wsum[8][O_];
    const int lane = tid & 31;
    const int w = tid >> 5;
    if (lane == 0)
        #pragma unroll
        for (int o = 0; o < O_; o++)
            wsum[w][o] = acc[o];
    __syncthreads();

    if (tid < O_) {
        float s = lin_b[tid];
        #pragma unroll
        for (int ww = 0; ww < 8; ww++)
            s += wsum[ww][tid];
        out[((size_t)b * T_ + t) * O_ + tid] = s;
    }
}

// ---------------------------------------------------------------------------
extern "C" void kernel_launch(void* const* d_in, const int* in_sizes, int n_in,
                              void* d_out, int out_size)
{
    const float* x     = (const float*)d_in[0];
    const float* h0    = (const float*)d_in[1];
    const float* Win   = (const float*)d_in[2];
    const float* W     = (const float*)d_in[3];
    const float* lin_w = (const float*)d_in[4];
    const float* lin_b = (const float*)d_in[5];
    float* out = (float*)d_out;

    __nv_bfloat16 *xhi, *xlo, *winT_hi, *winT_lo, *wT_hi, *wT_lo, *hA_hi, *hA_lo;
    cudaGetSymbolAddress((void**)&xhi, g_xhi);
    cudaGetSymbolAddress((void**)&xlo, g_xlo);
    cudaGetSymbolAddress((void**)&winT_hi, g_WinT_hi);
    cudaGetSymbolAddress((void**)&winT_lo, g_WinT_lo);
    cudaGetSymbolAddress((void**)&wT_hi, g_WT_hi);
    cudaGetSymbolAddress((void**)&wT_lo, g_WT_lo);
    cudaGetSymbolAddress((void**)&hA_hi, g_hA_hi);
    cudaGetSymbolAddress((void**)&hA_lo, g_hA_lo);

    static bool attr_done = false;
    if (!attr_done) {
        cudaFuncSetAttribute(xin_gemm_kernel,
                             cudaFuncAttributeMaxDynamicSharedMemorySize, SMEM_BYTES);
        cudaFuncSetAttribute(step_persistent_kernel,
                             cudaFuncAttributeMaxDynamicSharedMemorySize, SMEM_BYTES);
        attr_done = true;
    }

    // Prologue
    decomp_kernel<<<4096, 256>>>(x, xhi, xlo, (size_t)M1 * I_ / 4);
    decomp_kernel<<<512, 256>>>(h0, hA_hi, hA_lo, (size_t)B_ * H_ / 4);
    transpose_decomp_kernel<<<dim3(H_ / 32, I_ / 32), dim3(32, 8)>>>(Win, I_, H_, winT_hi, winT_lo);
    transpose_decomp_kernel<<<dim3(H_ / 32, H_ / 32), dim3(32, 8)>>>(W, H_, H_, wT_hi, wT_lo);

    // Input projection
    xin_gemm_kernel<<<dim3(H_ / BN, M1 / BM), 256, SMEM_BYTES>>>();

    // Full recurrence
    step_persistent_kernel<<<NBLK_STEP, 256, SMEM_BYTES>>>();

    // Output head
    out_kernel<<<T_ * B_, 256>>>(lin_w, lin_b, out);
}